// round 13
// baseline (speedup 1.0000x reference)
#include <cuda_runtime.h>
#include <math.h>
#include <stdint.h>

// ---------------- problem constants ----------------
#define Bsz   4
#define Ssz   2048
#define Esz   1024
#define Hsz   8
#define Mrows (Bsz * Ssz)          // 8192
#define N_UVQK 4096
#define N_PROJ 3072
#define ALPHA_SC 0.08838834764831845f   // 1/sqrt(128)
#define INV_S    (1.0f / 2048.0f)
#define LN_EPS   1e-6f

// ---------------- scratch (device globals; no allocation allowed) -----------
__device__ float g_normx[(size_t)Mrows * Esz];    // 32 MB (tf32-rounded)
__device__ float g_uvqk [(size_t)Mrows * N_UVQK]; // 128 MB (tf32-rounded)
__device__ float g_attn [(size_t)Mrows * Esz];    // 32 MB (full fp32)
__device__ float g_proj [(size_t)Mrows * N_PROJ]; // 96 MB (tf32-rounded)
__device__ float g_w1   [(size_t)Esz * N_UVQK];   // 16 MB rounded uvqk_w
__device__ float g_w2   [(size_t)N_PROJ * Esz];   // 12 MB rounded out_w

// ---------------- helpers ----------------
__device__ __forceinline__ uint32_t f2tf32(float x) {
    uint32_t r;
    asm("cvt.rna.tf32.f32 %0, %1;" : "=r"(r) : "f"(x));
    return r;
}
__device__ __forceinline__ float rnd32(float x) {
    return __uint_as_float(f2tf32(x));
}

__device__ __forceinline__ void mma_tf32(float* d,
    uint32_t a0, uint32_t a1, uint32_t a2, uint32_t a3,
    uint32_t b0, uint32_t b1)
{
    asm volatile(
        "mma.sync.aligned.m16n8k8.row.col.f32.tf32.tf32.f32 "
        "{%0,%1,%2,%3}, {%4,%5,%6,%7}, {%8,%9}, {%0,%1,%2,%3};\n"
        : "+f"(d[0]), "+f"(d[1]), "+f"(d[2]), "+f"(d[3])
        : "r"(a0), "r"(a1), "r"(a2), "r"(a3), "r"(b0), "r"(b1));
}

__device__ __forceinline__ float silu_f(float x) {
    return x / (1.0f + expf(-x));
}

__device__ __forceinline__ uint32_t smem_u32(const void* p) {
    uint32_t a;
    asm("{ .reg .u64 t; cvta.to.shared.u64 t, %1; cvt.u32.u64 %0, t; }"
        : "=r"(a) : "l"(p));
    return a;
}

__device__ __forceinline__ void cp_async16(uint32_t dst, const void* src) {
    asm volatile("cp.async.cg.shared.global [%0], [%1], 16;\n"
                 :: "r"(dst), "l"(src));
}
#define CP_COMMIT()  asm volatile("cp.async.commit_group;\n" ::: "memory")
#define CP_WAIT1()   asm volatile("cp.async.wait_group 1;\n" ::: "memory")

__device__ __forceinline__ void blockReduce2(float& a, float& b) {
    #pragma unroll
    for (int off = 16; off > 0; off >>= 1) {
        a += __shfl_down_sync(0xffffffffu, a, off);
        b += __shfl_down_sync(0xffffffffu, b, off);
    }
    __shared__ float sa[8], sb[8];
    __shared__ float ra, rb;
    int w = threadIdx.x >> 5, l = threadIdx.x & 31;
    if (l == 0) { sa[w] = a; sb[w] = b; }
    __syncthreads();
    if (threadIdx.x == 0) {
        float ta = 0.f, tb = 0.f;
        #pragma unroll
        for (int i = 0; i < 8; i++) { ta += sa[i]; tb += sb[i]; }
        ra = ta; rb = tb;
    }
    __syncthreads();
    a = ra; b = rb;
}

// ---------------- tf32 pre-round of weights ----------------
__global__ __launch_bounds__(256) void round_w_kernel(
    const float* __restrict__ src, float* __restrict__ dst, int n4)
{
    int i = (blockIdx.x * 256 + threadIdx.x);
    if (i < n4) {
        float4 v = *(const float4*)(src + (size_t)i * 4);
        v.x = rnd32(v.x); v.y = rnd32(v.y); v.z = rnd32(v.z); v.w = rnd32(v.w);
        *(float4*)(dst + (size_t)i * 4) = v;
    }
}

// ---------------- LayerNorm on input x -> g_normx (tf32-rounded) -----------
__global__ __launch_bounds__(256) void ln_in_kernel(
    const float* __restrict__ x, const float* __restrict__ sc,
    const float* __restrict__ bi, float* __restrict__ out)
{
    int row = blockIdx.x;
    int c = threadIdx.x * 4;
    const float* xr = x + (size_t)row * Esz;
    float4 v = *(const float4*)&xr[c];
    float s  = v.x + v.y + v.z + v.w;
    float ss = v.x*v.x + v.y*v.y + v.z*v.z + v.w*v.w;
    blockReduce2(s, ss);
    float mu = s * (1.0f / Esz);
    float rs = rsqrtf(ss * (1.0f / Esz) - mu * mu + LN_EPS);
    float4 s4 = *(const float4*)&sc[c];
    float4 b4 = *(const float4*)&bi[c];
    float4 o;
    o.x = rnd32((v.x - mu) * rs * s4.x + b4.x);
    o.y = rnd32((v.y - mu) * rs * s4.y + b4.y);
    o.z = rnd32((v.z - mu) * rs * s4.z + b4.z);
    o.w = rnd32((v.w - mu) * rs * s4.w + b4.w);
    *(float4*)&out[(size_t)row * Esz + c] = o;
}

// ---------------- tf32 mma.sync GEMM, cp.async 3-stage, 64x64 warp tiles ----
// A: MxK row-major fp32 (values already tf32-rounded). B: KxN likewise.
// Block tile 128x128, kTile 16, 3-stage cp.async pipeline, 128 threads
// (4 warps in 2(M) x 2(N), warp tile 64x64). LDS:MMA = 1:1 per k8-step.
// round_c != 0: store C values tf32-rounded (for uvqk consumed by attention).
#define GSTG_WORDS 4672
#define GEMM_SMEM_BYTES (3 * GSTG_WORDS * 4)   // 56064 B

__global__ __launch_bounds__(128, 2) void gemm_tf32_kernel(
    const float* __restrict__ A, const float* __restrict__ Bm,
    float* __restrict__ C, int M, int N, int K,
    const float* __restrict__ bias, const float* __restrict__ resid,
    float* __restrict__ silu_dst, int round_c)
{
    extern __shared__ __align__(16) uint32_t gsm[];
    uint32_t sbase = smem_u32(gsm);

    int tid = threadIdx.x;
    int wid = tid >> 5, lane = tid & 31;
    int gID = lane >> 2, tig = lane & 3;
    int warpM = wid & 1, warpN = wid >> 1;
    int bx = blockIdx.x, by = blockIdx.y;

    // A loader: 1 row per thread, 16 k-values (4 x cp.async 16B)
    int arow = tid;
    // B loader: 16 rows x 8 threads/row, 16 n-values each (4 x cp.async 16B)
    int brow = tid >> 3, bcol = (tid & 7) * 16;
    const float* Abase = A + (size_t)(by * 128 + arow) * K;
    const float* Bbase = Bm + (size_t)brow * N + bx * 128 + bcol;

    int nIter = K >> 4;

    auto issue_stage = [&](int c) {
        int s = c - (c / 3) * 3;
        uint32_t ab = sbase + (uint32_t)(s * GSTG_WORDS) * 4;
        uint32_t bb = ab + 2560 * 4;
        const float* ag = Abase + c * 16;
        #pragma unroll
        for (int x = 0; x < 4; x++)
            cp_async16(ab + (uint32_t)(arow * 20 + x * 4) * 4, ag + x * 4);
        const float* bg = Bbase + (size_t)(c * 16) * N;
        #pragma unroll
        for (int x = 0; x < 4; x++)
            cp_async16(bb + (uint32_t)(brow * 132 + bcol + x * 4) * 4, bg + x * 4);
    };

    float acc[4][8][4];
    #pragma unroll
    for (int i = 0; i < 4; i++)
        #pragma unroll
        for (int j = 0; j < 8; j++)
            #pragma unroll
            for (int q = 0; q < 4; q++) acc[i][j][q] = 0.f;

    issue_stage(0); CP_COMMIT();
    issue_stage(1); CP_COMMIT();

    for (int c = 0; c < nIter; c++) {
        CP_WAIT1();            // stage c resident
        __syncthreads();       // all warps done with stage c-1 compute; c visible
        if (c + 2 < nIter) issue_stage(c + 2);
        CP_COMMIT();           // always commit (empty group at tail keeps count)

        int s = c - (c / 3) * 3;
        const uint32_t* As = gsm + s * GSTG_WORDS;
        const uint32_t* Bs = As + 2560;
        #pragma unroll
        for (int ks = 0; ks < 2; ks++) {
            int kb = ks * 8;
            uint32_t af[4][4], bf[8][2];
            #pragma unroll
            for (int i = 0; i < 4; i++) {
                int m = warpM * 64 + i * 16 + gID;
                af[i][0] = As[m * 20 + kb + tig];
                af[i][1] = As[(m + 8) * 20 + kb + tig];
                af[i][2] = As[m * 20 + kb + tig + 4];
                af[i][3] = As[(m + 8) * 20 + kb + tig + 4];
            }
            #pragma unroll
            for (int j = 0; j < 8; j++) {
                int n = warpN * 64 + j * 8 + gID;
                bf[j][0] = Bs[(kb + tig) * 132 + n];
                bf[j][1] = Bs[(kb + tig + 4) * 132 + n];
            }
            #pragma unroll
            for (int i = 0; i < 4; i++)
                #pragma unroll
                for (int j = 0; j < 8; j++)
                    mma_tf32(acc[i][j], af[i][0], af[i][1], af[i][2], af[i][3],
                             bf[j][0], bf[j][1]);
        }
    }

    // epilogue
    bool siluTile = (silu_dst != nullptr) && (bx * 128 < 1024);
    #pragma unroll
    for (int i = 0; i < 4; i++) {
        int r0 = by * 128 + warpM * 64 + i * 16 + gID;
        #pragma unroll
        for (int j = 0; j < 8; j++) {
            int cg = bx * 128 + warpN * 64 + j * 8 + tig * 2;
            float v0 = acc[i][j][0], v1 = acc[i][j][1];
            float v2 = acc[i][j][2], v3 = acc[i][j][3];
            if (bias) {
                float b0 = bias[cg], b1 = bias[cg + 1];
                v0 += b0; v1 += b1; v2 += b0; v3 += b1;
            }
            size_t o0 = (size_t)r0 * N + cg;
            size_t o1 = (size_t)(r0 + 8) * N + cg;
            if (resid) {
                v0 += resid[o0]; v1 += resid[o0 + 1];
                v2 += resid[o1]; v3 += resid[o1 + 1];
            }
            if (round_c) {
                *(float2*)&C[o0] = make_float2(rnd32(v0), rnd32(v1));
                *(float2*)&C[o1] = make_float2(rnd32(v2), rnd32(v3));
            } else {
                *(float2*)&C[o0] = make_float2(v0, v1);
                *(float2*)&C[o1] = make_float2(v2, v3);
            }
            if (siluTile) {
                size_t p0 = (size_t)r0 * N_PROJ + cg;
                size_t p1 = (size_t)(r0 + 8) * N_PROJ + cg;
                *(float2*)&silu_dst[p0] =
                    make_float2(rnd32(silu_f(v0)), rnd32(silu_f(v1)));
                *(float2*)&silu_dst[p1] =
                    make_float2(rnd32(silu_f(v2)), rnd32(silu_f(v3)));
            }
        }
    }
}

// ---------------- cp.async-pipelined tensor-core attention ------------------
// block = (b, h, 64 q rows). 256 threads / 8 warps. K-tiles of 64, causal skip.
// uvqk values are pre-rounded to tf32, so tiles are loaded as raw bytes via
// cp.async with one-tile lookahead (double-buffered K/V stages).
// smem words: Qs[64][132]@0   K stages @8448,@16896
//             V stages @25344,@33792   Ws[64][68]@42240
// total 46592 words = 186368 B
#define AQ(r,c)    sm[(r) * 132 + (c)]
#define AK(s,r,c)  sm[8448 + (s) * 8448 + (r) * 132 + (c)]
#define AV(s,r,c)  sm[25344 + (s) * 8448 + (r) * 132 + (c)]
#define AW(r,c)    sm[42240 + (r) * 68 + (c)]
#define ATTN_SMEM_BYTES (46592 * 4)

__global__ __launch_bounds__(256) void attn_tc_kernel(
    const float* __restrict__ uvqk, const int* __restrict__ num_targets,
    float* __restrict__ attn_out)
{
    extern __shared__ uint32_t sm[];
    uint32_t sbase = smem_u32(sm);
    int tid = threadIdx.x;
    int wid = tid >> 5, lane = tid & 31;
    int gID = lane >> 2, tig = lane & 3;
    int b = blockIdx.z, h = blockIdx.y;
    int q0 = blockIdx.x * 64;
    int maxid = Ssz - num_targets[b];

    const size_t rstride = N_UVQK;
    const float* qbase = uvqk + (size_t)(b * Ssz) * rstride + 2048 + h * 128;
    const float* kbase = uvqk + (size_t)(b * Ssz) * rstride + 3072 + h * 128;
    const float* vbase = uvqk + (size_t)(b * Ssz) * rstride + 1024 + h * 128;

    int ldr = tid >> 2, ldc = (tid & 3) * 32;

    // Q tile via cp.async (group 0)
    {
        const float* qsrc = qbase + (size_t)(q0 + ldr) * rstride + ldc;
        #pragma unroll
        for (int x = 0; x < 8; x++)
            cp_async16(sbase + (uint32_t)(ldr * 132 + ldc + x * 4) * 4,
                       qsrc + x * 4);
    }
    CP_COMMIT();

    auto issue_kv = [&](int t) {
        int s = t & 1;
        const float* ksrc = kbase + (size_t)(t * 64 + ldr) * rstride + ldc;
        const float* vsrc = vbase + (size_t)(t * 64 + ldr) * rstride + ldc;
        uint32_t kdst = sbase + (uint32_t)(8448 + s * 8448 + ldr * 132 + ldc) * 4;
        uint32_t vdst = sbase + (uint32_t)(25344 + s * 8448 + ldr * 132 + ldc) * 4;
        #pragma unroll
        for (int x = 0; x < 8; x++) {
            cp_async16(kdst + x * 16, ksrc + x * 4);
            cp_async16(vdst + x * 16, vsrc + x * 4);
        }
    };

    issue_kv(0); CP_COMMIT();      // group 1

    int sWM = wid & 3, sWN = wid >> 2;
    int oWM = wid & 1, oWN = wid >> 1;

    float acc_o[2][4][4];
    #pragma unroll
    for (int i = 0; i < 2; i++)
        #pragma unroll
        for (int j = 0; j < 4; j++)
            #pragma unroll
            for (int q = 0; q < 4; q++) acc_o[i][j][q] = 0.f;

    int ntiles = q0 / 64 + 1;

    for (int t = 0; t < ntiles; t++) {
        int s = t & 1;
        __syncthreads();   // everyone done with stage s from iter t-2 and Ws
        if (t + 1 < ntiles) issue_kv(t + 1);
        CP_COMMIT();       // always commit (empty tail groups keep the count)
        CP_WAIT1();        // tile t (and Q) resident; t+1 may be in flight
        __syncthreads();   // cross-thread visibility of cp.async data

        // scores: S(64x64) = Q(64x128) @ K^T
        float acc_s[4][4];
        #pragma unroll
        for (int j = 0; j < 4; j++)
            #pragma unroll
            for (int q = 0; q < 4; q++) acc_s[j][q] = 0.f;

        #pragma unroll
        for (int ks = 0; ks < 16; ks++) {
            int kb = ks * 8;
            int m = sWM * 16 + gID;
            uint32_t a0 = AQ(m, kb + tig);
            uint32_t a1 = AQ(m + 8, kb + tig);
            uint32_t a2 = AQ(m, kb + tig + 4);
            uint32_t a3 = AQ(m + 8, kb + tig + 4);
            #pragma unroll
            for (int j = 0; j < 4; j++) {
                int n = sWN * 32 + j * 8 + gID;
                uint32_t b0 = AK(s, n, kb + tig);
                uint32_t b1 = AK(s, n, kb + tig + 4);
                mma_tf32(acc_s[j], a0, a1, a2, a3, b0, b1);
            }
        }

        // mask + silu -> Ws
        {
            int k0 = t * 64;
            int rowL = sWM * 16 + gID;
            int qg0 = q0 + rowL;
            int qg1 = qg0 + 8;
            int idq0 = min(qg0, maxid);
            int idq1 = min(qg1, maxid);
            #pragma unroll
            for (int j = 0; j < 4; j++) {
                int colL = sWN * 32 + j * 8 + tig * 2;
                #pragma unroll
                for (int cc = 0; cc < 2; cc++) {
                    int kg = k0 + colL + cc;
                    int idk = min(kg, maxid);
                    float s0 = acc_s[j][cc] * ALPHA_SC;
                    float s1 = acc_s[j][cc + 2] * ALPHA_SC;
                    bool v0 = (qg0 == kg) || (idq0 > idk);
                    bool v1 = (qg1 == kg) || (idq1 > idk);
                    float w0 = v0 ? silu_f(s0) * INV_S : 0.f;
                    float w1 = v1 ? silu_f(s1) * INV_S : 0.f;
                    AW(rowL, colL + cc)     = f2tf32(w0);
                    AW(rowL + 8, colL + cc) = f2tf32(w1);
                }
            }
        }
        __syncthreads();

        // O += Ws(64x64) @ V(64x128)
        #pragma unroll
        for (int ks = 0; ks < 8; ks++) {
            int kb = ks * 8;
            uint32_t af[2][4];
            #pragma unroll
            for (int i = 0; i < 2; i++) {
                int m = oWM * 32 + i * 16 + gID;
                af[i][0] = AW(m, kb + tig);
                af[i][1] = AW(m + 8, kb + tig);
                af[i][2] = AW(m, kb + tig + 4);
                af[i][3] = AW(m + 8, kb + tig + 4);
            }
            #pragma unroll
            for (int j = 0; j < 4; j++) {
                int n = oWN * 32 + j * 8 + gID;
                uint32_t b0 = AV(s, kb + tig, n);
                uint32_t b1 = AV(s, kb + tig + 4, n);
                #pragma unroll
                for (int i = 0; i < 2; i++)
                    mma_tf32(acc_o[i][j], af[i][0], af[i][1], af[i][2], af[i][3],
                             b0, b1);
            }
        }
    }

    #pragma unroll
    for (int i = 0; i < 2; i++) {
        int rowL = oWM * 32 + i * 16 + gID;
        size_t grow0 = (size_t)(b * Ssz + q0 + rowL) * Esz;
        size_t grow1 = (size_t)(b * Ssz + q0 + rowL + 8) * Esz;
        #pragma unroll
        for (int j = 0; j < 4; j++) {
            int col = h * 128 + oWN * 32 + j * 8 + tig * 2;
            *(float2*)&attn_out[grow0 + col] = make_float2(acc_o[i][j][0], acc_o[i][j][1]);
            *(float2*)&attn_out[grow1 + col] = make_float2(acc_o[i][j][2], acc_o[i][j][3]);
        }
    }
}

// ---------------- post-attention: LN(attn), gate, fill proj (tf32-rounded) --
__global__ __launch_bounds__(256) void postattn_kernel(
    const float* __restrict__ attn, const float* __restrict__ sc,
    const float* __restrict__ bi, float* __restrict__ proj)
{
    int row = blockIdx.x;
    int c = threadIdx.x * 4;
    const float* ar = attn + (size_t)row * Esz;
    float4 a = *(const float4*)&ar[c];
    float s  = a.x + a.y + a.z + a.w;
    float ss = a.x*a.x + a.y*a.y + a.z*a.z + a.w*a.w;
    blockReduce2(s, ss);
    float mu = s * (1.0f / Esz);
    float rs = rsqrtf(ss * (1.0f / Esz) - mu * mu + LN_EPS);
    float4 s4 = *(const float4*)&sc[c];
    float4 b4 = *(const float4*)&bi[c];
    float4 n;
    n.x = (a.x - mu) * rs * s4.x + b4.x;
    n.y = (a.y - mu) * rs * s4.y + b4.y;
    n.z = (a.z - mu) * rs * s4.z + b4.z;
    n.w = (a.w - mu) * rs * s4.w + b4.w;
    float* pr = proj + (size_t)row * N_PROJ;
    float4 u = *(const float4*)&pr[c];         // silu(u), already tf32-rounded
    float4 ar4;
    ar4.x = rnd32(a.x); ar4.y = rnd32(a.y); ar4.z = rnd32(a.z); ar4.w = rnd32(a.w);
    *(float4*)&pr[1024 + c] = ar4;
    float4 g;
    g.x = rnd32(u.x * n.x); g.y = rnd32(u.y * n.y);
    g.z = rnd32(u.z * n.z); g.w = rnd32(u.w * n.w);
    *(float4*)&pr[2048 + c] = g;
}

// ---------------- launch ----------------
extern "C" void kernel_launch(void* const* d_in, const int* in_sizes, int n_in,
                              void* d_out, int out_size)
{
    const float* x           = (const float*)d_in[0];
    const int*   num_targets = (const int*)  d_in[1];
    const float* uvqk_w      = (const float*)d_in[2];
    const float* uvqk_beta   = (const float*)d_in[3];
    const float* out_w       = (const float*)d_in[4];
    const float* in_scale    = (const float*)d_in[5];
    const float* in_bias     = (const float*)d_in[6];
    const float* out_scale   = (const float*)d_in[7];
    const float* out_bias    = (const float*)d_in[8];
    float* out = (float*)d_out;

    float *normx, *uvqk, *attn, *proj, *w1, *w2;
    cudaGetSymbolAddress((void**)&normx, g_normx);
    cudaGetSymbolAddress((void**)&uvqk,  g_uvqk);
    cudaGetSymbolAddress((void**)&attn,  g_attn);
    cudaGetSymbolAddress((void**)&proj,  g_proj);
    cudaGetSymbolAddress((void**)&w1,    g_w1);
    cudaGetSymbolAddress((void**)&w2,    g_w2);

    // idempotent, capture-safe; no static state
    cudaFuncSetAttribute(attn_tc_kernel,
                         cudaFuncAttributeMaxDynamicSharedMemorySize,
                         ATTN_SMEM_BYTES);
    cudaFuncSetAttribute(gemm_tf32_kernel,
                         cudaFuncAttributeMaxDynamicSharedMemorySize,
                         GEMM_SMEM_BYTES);

    // 0) pre-round weights to tf32 values
    round_w_kernel<<<(Esz * N_UVQK / 4 + 255) / 256, 256>>>(uvqk_w, w1, Esz * N_UVQK / 4);
    round_w_kernel<<<(N_PROJ * Esz / 4 + 255) / 256, 256>>>(out_w, w2, N_PROJ * Esz / 4);

    // 1) LayerNorm input (tf32-rounded output)
    ln_in_kernel<<<Mrows, 256>>>(x, in_scale, in_bias, normx);

    // 2) UVQK GEMM: + beta, silu(u) tap, C stored tf32-rounded for attention
    gemm_tf32_kernel<<<dim3(N_UVQK / 128, Mrows / 128), 128, GEMM_SMEM_BYTES>>>(
        normx, w1, uvqk, Mrows, N_UVQK, Esz, uvqk_beta, nullptr, proj, 1);

    // 3) cp.async-pipelined tensor-core attention (causal-skip) -> attn
    attn_tc_kernel<<<dim3(Ssz / 64, Hsz, Bsz), 256, ATTN_SMEM_BYTES>>>(
        uvqk, num_targets, attn);

    // 4) LN(attn) + gate (tf32-rounded proj entries)
    postattn_kernel<<<Mrows, 256>>>(attn, out_scale, out_bias, proj);

    // 5) output GEMM with fused residual (exact fp32 output)
    gemm_tf32_kernel<<<dim3(Esz / 128, Mrows / 128), 128, GEMM_SMEM_BYTES>>>(
        proj, w2, out, Mrows, Esz, N_PROJ, nullptr, x, nullptr, 0);
}

// round 14
// speedup vs baseline: 1.1688x; 1.1688x over previous
#include <cuda_runtime.h>
#include <math.h>
#include <stdint.h>

// ---------------- problem constants ----------------
#define Bsz   4
#define Ssz   2048
#define Esz   1024
#define Hsz   8
#define Mrows (Bsz * Ssz)          // 8192
#define N_UVQK 4096
#define N_PROJ 3072
#define ALPHA_SC 0.08838834764831845f   // 1/sqrt(128)
#define INV_S    (1.0f / 2048.0f)
#define LN_EPS   1e-6f

// ---------------- scratch (device globals; no allocation allowed) -----------
__device__ float g_normx[(size_t)Mrows * Esz];    // 32 MB (tf32-rounded)
__device__ float g_uvqk [(size_t)Mrows * N_UVQK]; // 128 MB (tf32-rounded)
__device__ float g_attn [(size_t)Mrows * Esz];    // 32 MB (full fp32)
__device__ float g_proj [(size_t)Mrows * N_PROJ]; // 96 MB (tf32-rounded)
__device__ float g_w1   [(size_t)Esz * N_UVQK];   // 16 MB rounded uvqk_w
__device__ float g_w2   [(size_t)N_PROJ * Esz];   // 12 MB rounded out_w

// ---------------- helpers ----------------
__device__ __forceinline__ uint32_t f2tf32(float x) {
    uint32_t r;
    asm("cvt.rna.tf32.f32 %0, %1;" : "=r"(r) : "f"(x));
    return r;
}
__device__ __forceinline__ float rnd32(float x) {
    return __uint_as_float(f2tf32(x));
}

__device__ __forceinline__ void mma_tf32(float* d,
    uint32_t a0, uint32_t a1, uint32_t a2, uint32_t a3,
    uint32_t b0, uint32_t b1)
{
    asm volatile(
        "mma.sync.aligned.m16n8k8.row.col.f32.tf32.tf32.f32 "
        "{%0,%1,%2,%3}, {%4,%5,%6,%7}, {%8,%9}, {%0,%1,%2,%3};\n"
        : "+f"(d[0]), "+f"(d[1]), "+f"(d[2]), "+f"(d[3])
        : "r"(a0), "r"(a1), "r"(a2), "r"(a3), "r"(b0), "r"(b1));
}

__device__ __forceinline__ float silu_f(float x) {
    return x / (1.0f + expf(-x));
}

__device__ __forceinline__ uint32_t smem_u32(const void* p) {
    uint32_t a;
    asm("{ .reg .u64 t; cvta.to.shared.u64 t, %1; cvt.u32.u64 %0, t; }"
        : "=r"(a) : "l"(p));
    return a;
}

__device__ __forceinline__ void cp_async16(uint32_t dst, const void* src) {
    asm volatile("cp.async.cg.shared.global [%0], [%1], 16;\n"
                 :: "r"(dst), "l"(src));
}
#define CP_COMMIT()  asm volatile("cp.async.commit_group;\n" ::: "memory")
#define CP_WAIT1()   asm volatile("cp.async.wait_group 1;\n" ::: "memory")
#define CP_WAIT2()   asm volatile("cp.async.wait_group 2;\n" ::: "memory")

__device__ __forceinline__ void blockReduce2(float& a, float& b) {
    #pragma unroll
    for (int off = 16; off > 0; off >>= 1) {
        a += __shfl_down_sync(0xffffffffu, a, off);
        b += __shfl_down_sync(0xffffffffu, b, off);
    }
    __shared__ float sa[8], sb[8];
    __shared__ float ra, rb;
    int w = threadIdx.x >> 5, l = threadIdx.x & 31;
    if (l == 0) { sa[w] = a; sb[w] = b; }
    __syncthreads();
    if (threadIdx.x == 0) {
        float ta = 0.f, tb = 0.f;
        #pragma unroll
        for (int i = 0; i < 8; i++) { ta += sa[i]; tb += sb[i]; }
        ra = ta; rb = tb;
    }
    __syncthreads();
    a = ra; b = rb;
}

// ---------------- tf32 pre-round of weights ----------------
__global__ __launch_bounds__(256) void round_w_kernel(
    const float* __restrict__ src, float* __restrict__ dst, int n4)
{
    int i = (blockIdx.x * 256 + threadIdx.x);
    if (i < n4) {
        float4 v = *(const float4*)(src + (size_t)i * 4);
        v.x = rnd32(v.x); v.y = rnd32(v.y); v.z = rnd32(v.z); v.w = rnd32(v.w);
        *(float4*)(dst + (size_t)i * 4) = v;
    }
}

// ---------------- LayerNorm on input x -> g_normx (tf32-rounded) -----------
__global__ __launch_bounds__(256) void ln_in_kernel(
    const float* __restrict__ x, const float* __restrict__ sc,
    const float* __restrict__ bi, float* __restrict__ out)
{
    int row = blockIdx.x;
    int c = threadIdx.x * 4;
    const float* xr = x + (size_t)row * Esz;
    float4 v = *(const float4*)&xr[c];
    float s  = v.x + v.y + v.z + v.w;
    float ss = v.x*v.x + v.y*v.y + v.z*v.z + v.w*v.w;
    blockReduce2(s, ss);
    float mu = s * (1.0f / Esz);
    float rs = rsqrtf(ss * (1.0f / Esz) - mu * mu + LN_EPS);
    float4 s4 = *(const float4*)&sc[c];
    float4 b4 = *(const float4*)&bi[c];
    float4 o;
    o.x = rnd32((v.x - mu) * rs * s4.x + b4.x);
    o.y = rnd32((v.y - mu) * rs * s4.y + b4.y);
    o.z = rnd32((v.z - mu) * rs * s4.z + b4.z);
    o.w = rnd32((v.w - mu) * rs * s4.w + b4.w);
    *(float4*)&out[(size_t)row * Esz + c] = o;
}

// ---------------- tf32 mma.sync GEMM, cp.async 3-stage (R12 config) ---------
// A: MxK row-major fp32 (values already tf32-rounded). B: KxN likewise.
// Block tile 128x128, kTile 16, 256 threads, 8 warps 2(M)x4(N) 64x32 tiles.
#define GSTG_WORDS 4672
#define GEMM_SMEM_BYTES (3 * GSTG_WORDS * 4)   // 56064 B

__global__ __launch_bounds__(256, 2) void gemm_tf32_kernel(
    const float* __restrict__ A, const float* __restrict__ Bm,
    float* __restrict__ C, int M, int N, int K,
    const float* __restrict__ bias, const float* __restrict__ resid,
    float* __restrict__ silu_dst, int round_c)
{
    extern __shared__ __align__(16) uint32_t gsm[];
    uint32_t sbase = smem_u32(gsm);

    int tid = threadIdx.x;
    int wid = tid >> 5, lane = tid & 31;
    int gID = lane >> 2, tig = lane & 3;
    int warpM = wid & 1, warpN = wid >> 1;
    int bx = blockIdx.x, by = blockIdx.y;

    int arow = tid >> 1, acol = (tid & 1) * 8;
    int brow = tid >> 4, bcol = (tid & 15) * 8;
    const float* Abase = A + (size_t)(by * 128 + arow) * K + acol;
    const float* Bbase = Bm + (size_t)brow * N + bx * 128 + bcol;

    int nIter = K >> 4;

    auto issue_stage = [&](int c) {
        int s = c - (c / 3) * 3;
        uint32_t ab = sbase + (uint32_t)(s * GSTG_WORDS) * 4;
        uint32_t bb = ab + 2560 * 4;
        const float* ag = Abase + c * 16;
        cp_async16(ab + (uint32_t)(arow * 20 + acol) * 4, ag);
        cp_async16(ab + (uint32_t)(arow * 20 + acol + 4) * 4, ag + 4);
        const float* bg = Bbase + (size_t)(c * 16) * N;
        cp_async16(bb + (uint32_t)(brow * 132 + bcol) * 4, bg);
        cp_async16(bb + (uint32_t)(brow * 132 + bcol + 4) * 4, bg + 4);
    };

    float acc[4][4][4];
    #pragma unroll
    for (int i = 0; i < 4; i++)
        #pragma unroll
        for (int j = 0; j < 4; j++)
            #pragma unroll
            for (int q = 0; q < 4; q++) acc[i][j][q] = 0.f;

    issue_stage(0); CP_COMMIT();
    issue_stage(1); CP_COMMIT();

    for (int c = 0; c < nIter; c++) {
        CP_WAIT1();
        __syncthreads();
        if (c + 2 < nIter) issue_stage(c + 2);
        CP_COMMIT();

        int s = c - (c / 3) * 3;
        const uint32_t* As = gsm + s * GSTG_WORDS;
        const uint32_t* Bs = As + 2560;
        #pragma unroll
        for (int ks = 0; ks < 2; ks++) {
            int kb = ks * 8;
            uint32_t af[4][4], bf[4][2];
            #pragma unroll
            for (int i = 0; i < 4; i++) {
                int m = warpM * 64 + i * 16 + gID;
                af[i][0] = As[m * 20 + kb + tig];
                af[i][1] = As[(m + 8) * 20 + kb + tig];
                af[i][2] = As[m * 20 + kb + tig + 4];
                af[i][3] = As[(m + 8) * 20 + kb + tig + 4];
            }
            #pragma unroll
            for (int j = 0; j < 4; j++) {
                int n = warpN * 32 + j * 8 + gID;
                bf[j][0] = Bs[(kb + tig) * 132 + n];
                bf[j][1] = Bs[(kb + tig + 4) * 132 + n];
            }
            #pragma unroll
            for (int i = 0; i < 4; i++)
                #pragma unroll
                for (int j = 0; j < 4; j++)
                    mma_tf32(acc[i][j], af[i][0], af[i][1], af[i][2], af[i][3],
                             bf[j][0], bf[j][1]);
        }
    }

    // epilogue
    bool siluTile = (silu_dst != nullptr) && (bx * 128 < 1024);
    #pragma unroll
    for (int i = 0; i < 4; i++) {
        int r0 = by * 128 + warpM * 64 + i * 16 + gID;
        #pragma unroll
        for (int j = 0; j < 4; j++) {
            int cg = bx * 128 + warpN * 32 + j * 8 + tig * 2;
            float v0 = acc[i][j][0], v1 = acc[i][j][1];
            float v2 = acc[i][j][2], v3 = acc[i][j][3];
            if (bias) {
                float b0 = bias[cg], b1 = bias[cg + 1];
                v0 += b0; v1 += b1; v2 += b0; v3 += b1;
            }
            size_t o0 = (size_t)r0 * N + cg;
            size_t o1 = (size_t)(r0 + 8) * N + cg;
            if (resid) {
                v0 += resid[o0]; v1 += resid[o0 + 1];
                v2 += resid[o1]; v3 += resid[o1 + 1];
            }
            if (round_c) {
                *(float2*)&C[o0] = make_float2(rnd32(v0), rnd32(v1));
                *(float2*)&C[o1] = make_float2(rnd32(v2), rnd32(v3));
            } else {
                *(float2*)&C[o0] = make_float2(v0, v1);
                *(float2*)&C[o1] = make_float2(v2, v3);
            }
            if (siluTile) {
                size_t p0 = (size_t)r0 * N_PROJ + cg;
                size_t p1 = (size_t)(r0 + 8) * N_PROJ + cg;
                *(float2*)&silu_dst[p0] =
                    make_float2(rnd32(silu_f(v0)), rnd32(silu_f(v1)));
                *(float2*)&silu_dst[p1] =
                    make_float2(rnd32(silu_f(v2)), rnd32(silu_f(v3)));
            }
        }
    }
}

// ---------------- cp.async-pipelined attention, 128-row Q tiles -------------
// block = (b, h, 128 q rows). 256 threads / 8 warps: 4(M) x 2(N) for both
// phases. Score warp tile 32x32; W@V warp tile 32x64. K double-buffered with
// one-tile lookahead; V single-buffered (latency hidden under score phase).
// smem words: Q[128][132]@0  Kst 2x[64][132]@16896,@25344
//             V[64][132]@33792  Ws[128][68]@42240   total 50944 w = 203776 B
#define AQ(r,c)    sm[(r) * 132 + (c)]
#define AK(s,r,c)  sm[16896 + (s) * 8448 + (r) * 132 + (c)]
#define AV(r,c)    sm[33792 + (r) * 132 + (c)]
#define AW(r,c)    sm[42240 + (r) * 68 + (c)]
#define ATTN_SMEM_BYTES (50944 * 4)

__global__ __launch_bounds__(256) void attn_tc_kernel(
    const float* __restrict__ uvqk, const int* __restrict__ num_targets,
    float* __restrict__ attn_out)
{
    extern __shared__ uint32_t sm[];
    uint32_t sbase = smem_u32(sm);
    int tid = threadIdx.x;
    int wid = tid >> 5, lane = tid & 31;
    int gID = lane >> 2, tig = lane & 3;
    int b = blockIdx.z, h = blockIdx.y;
    int qt = (int)gridDim.x - 1 - (int)blockIdx.x;   // heavy blocks first
    int q0 = qt * 128;
    int maxid = Ssz - num_targets[b];

    const size_t rstride = N_UVQK;
    const float* qbase = uvqk + (size_t)(b * Ssz) * rstride + 2048 + h * 128;
    const float* kbase = uvqk + (size_t)(b * Ssz) * rstride + 3072 + h * 128;
    const float* vbase = uvqk + (size_t)(b * Ssz) * rstride + 1024 + h * 128;

    int ldr = tid >> 2, ldc = (tid & 3) * 32;   // 64-row tile loader
    int qr = tid >> 1, qc = (tid & 1) * 64;     // 128-row Q loader

    // Q tile 128x128 via cp.async (group 0)
    {
        const float* qsrc = qbase + (size_t)(q0 + qr) * rstride + qc;
        #pragma unroll
        for (int x = 0; x < 16; x++)
            cp_async16(sbase + (uint32_t)(qr * 132 + qc + x * 4) * 4,
                       qsrc + x * 4);
    }
    CP_COMMIT();

    auto issue_k = [&](int t) {
        int s = t & 1;
        const float* ksrc = kbase + (size_t)(t * 64 + ldr) * rstride + ldc;
        uint32_t kdst = sbase + (uint32_t)(16896 + s * 8448 + ldr * 132 + ldc) * 4;
        #pragma unroll
        for (int x = 0; x < 8; x++)
            cp_async16(kdst + x * 16, ksrc + x * 4);
    };
    auto issue_v = [&](int t) {
        const float* vsrc = vbase + (size_t)(t * 64 + ldr) * rstride + ldc;
        uint32_t vdst = sbase + (uint32_t)(33792 + ldr * 132 + ldc) * 4;
        #pragma unroll
        for (int x = 0; x < 8; x++)
            cp_async16(vdst + x * 16, vsrc + x * 4);
    };

    issue_k(0); CP_COMMIT();       // group 1

    int wM = wid & 3, wN = wid >> 2;

    float acc_o[2][8][4];
    #pragma unroll
    for (int i = 0; i < 2; i++)
        #pragma unroll
        for (int j = 0; j < 8; j++)
            #pragma unroll
            for (int q = 0; q < 4; q++) acc_o[i][j][q] = 0.f;

    int ntiles = q0 / 64 + 2;       // k tiles: k0 <= q0 + 64

    for (int t = 0; t < ntiles; t++) {
        int s = t & 1;
        __syncthreads();    // V buffer + Ws free (W@V of t-1 done); K stage s free
        issue_v(t); CP_COMMIT();
        if (t + 1 < ntiles) issue_k(t + 1);
        CP_COMMIT();        // always commit (empty tail keeps group count)
        CP_WAIT2();         // K(t) + Q resident; V(t), K(t+1) may be in flight
        __syncthreads();    // visibility of K(t)

        // scores: S(128x64) = Q(128x128) @ K^T; warp tile 32x32
        float acc_s[2][4][4];
        #pragma unroll
        for (int i = 0; i < 2; i++)
            #pragma unroll
            for (int j = 0; j < 4; j++)
                #pragma unroll
                for (int q = 0; q < 4; q++) acc_s[i][j][q] = 0.f;

        #pragma unroll
        for (int ks = 0; ks < 16; ks++) {
            int kb = ks * 8;
            uint32_t af[2][4];
            #pragma unroll
            for (int i = 0; i < 2; i++) {
                int m = wM * 32 + i * 16 + gID;
                af[i][0] = AQ(m, kb + tig);
                af[i][1] = AQ(m + 8, kb + tig);
                af[i][2] = AQ(m, kb + tig + 4);
                af[i][3] = AQ(m + 8, kb + tig + 4);
            }
            #pragma unroll
            for (int j = 0; j < 4; j++) {
                int n = wN * 32 + j * 8 + gID;
                uint32_t b0 = AK(s, n, kb + tig);
                uint32_t b1 = AK(s, n, kb + tig + 4);
                #pragma unroll
                for (int i = 0; i < 2; i++)
                    mma_tf32(acc_s[i][j], af[i][0], af[i][1], af[i][2], af[i][3],
                             b0, b1);
            }
        }

        // mask + silu -> Ws
        {
            int k0 = t * 64;
            #pragma unroll
            for (int i = 0; i < 2; i++) {
                int rowL = wM * 32 + i * 16 + gID;
                int qg0 = q0 + rowL;
                int qg1 = qg0 + 8;
                int idq0 = min(qg0, maxid);
                int idq1 = min(qg1, maxid);
                #pragma unroll
                for (int j = 0; j < 4; j++) {
                    int colL = wN * 32 + j * 8 + tig * 2;
                    #pragma unroll
                    for (int cc = 0; cc < 2; cc++) {
                        int kg = k0 + colL + cc;
                        int idk = min(kg, maxid);
                        float s0 = acc_s[i][j][cc] * ALPHA_SC;
                        float s1 = acc_s[i][j][cc + 2] * ALPHA_SC;
                        bool v0 = (qg0 == kg) || (idq0 > idk);
                        bool v1 = (qg1 == kg) || (idq1 > idk);
                        float w0 = v0 ? silu_f(s0) * INV_S : 0.f;
                        float w1 = v1 ? silu_f(s1) * INV_S : 0.f;
                        AW(rowL, colL + cc)     = f2tf32(w0);
                        AW(rowL + 8, colL + cc) = f2tf32(w1);
                    }
                }
            }
        }
        CP_WAIT1();         // V(t) resident; only K(t+1) may remain in flight
        __syncthreads();    // Ws + V visible to all warps

        // O += Ws(128x64) @ V(64x128); warp tile 32x64
        #pragma unroll
        for (int ks = 0; ks < 8; ks++) {
            int kb = ks * 8;
            uint32_t af[2][4];
            #pragma unroll
            for (int i = 0; i < 2; i++) {
                int m = wM * 32 + i * 16 + gID;
                af[i][0] = AW(m, kb + tig);
                af[i][1] = AW(m + 8, kb + tig);
                af[i][2] = AW(m, kb + tig + 4);
                af[i][3] = AW(m + 8, kb + tig + 4);
            }
            #pragma unroll
            for (int j = 0; j < 8; j++) {
                int n = wN * 64 + j * 8 + gID;
                uint32_t b0 = AV(kb + tig, n);
                uint32_t b1 = AV(kb + tig + 4, n);
                #pragma unroll
                for (int i = 0; i < 2; i++)
                    mma_tf32(acc_o[i][j], af[i][0], af[i][1], af[i][2], af[i][3],
                             b0, b1);
            }
        }
    }

    // epilogue
    #pragma unroll
    for (int i = 0; i < 2; i++) {
        int rowL = wM * 32 + i * 16 + gID;
        size_t grow0 = (size_t)(b * Ssz + q0 + rowL) * Esz;
        size_t grow1 = (size_t)(b * Ssz + q0 + rowL + 8) * Esz;
        #pragma unroll
        for (int j = 0; j < 8; j++) {
            int col = h * 128 + wN * 64 + j * 8 + tig * 2;
            *(float2*)&attn_out[grow0 + col] = make_float2(acc_o[i][j][0], acc_o[i][j][1]);
            *(float2*)&attn_out[grow1 + col] = make_float2(acc_o[i][j][2], acc_o[i][j][3]);
        }
    }
}

// ---------------- post-attention: LN(attn), gate, fill proj (tf32-rounded) --
__global__ __launch_bounds__(256) void postattn_kernel(
    const float* __restrict__ attn, const float* __restrict__ sc,
    const float* __restrict__ bi, float* __restrict__ proj)
{
    int row = blockIdx.x;
    int c = threadIdx.x * 4;
    const float* ar = attn + (size_t)row * Esz;
    float4 a = *(const float4*)&ar[c];
    float s  = a.x + a.y + a.z + a.w;
    float ss = a.x*a.x + a.y*a.y + a.z*a.z + a.w*a.w;
    blockReduce2(s, ss);
    float mu = s * (1.0f / Esz);
    float rs = rsqrtf(ss * (1.0f / Esz) - mu * mu + LN_EPS);
    float4 s4 = *(const float4*)&sc[c];
    float4 b4 = *(const float4*)&bi[c];
    float4 n;
    n.x = (a.x - mu) * rs * s4.x + b4.x;
    n.y = (a.y - mu) * rs * s4.y + b4.y;
    n.z = (a.z - mu) * rs * s4.z + b4.z;
    n.w = (a.w - mu) * rs * s4.w + b4.w;
    float* pr = proj + (size_t)row * N_PROJ;
    float4 u = *(const float4*)&pr[c];         // silu(u), already tf32-rounded
    float4 ar4;
    ar4.x = rnd32(a.x); ar4.y = rnd32(a.y); ar4.z = rnd32(a.z); ar4.w = rnd32(a.w);
    *(float4*)&pr[1024 + c] = ar4;
    float4 g;
    g.x = rnd32(u.x * n.x); g.y = rnd32(u.y * n.y);
    g.z = rnd32(u.z * n.z); g.w = rnd32(u.w * n.w);
    *(float4*)&pr[2048 + c] = g;
}

// ---------------- launch ----------------
extern "C" void kernel_launch(void* const* d_in, const int* in_sizes, int n_in,
                              void* d_out, int out_size)
{
    const float* x           = (const float*)d_in[0];
    const int*   num_targets = (const int*)  d_in[1];
    const float* uvqk_w      = (const float*)d_in[2];
    const float* uvqk_beta   = (const float*)d_in[3];
    const float* out_w       = (const float*)d_in[4];
    const float* in_scale    = (const float*)d_in[5];
    const float* in_bias     = (const float*)d_in[6];
    const float* out_scale   = (const float*)d_in[7];
    const float* out_bias    = (const float*)d_in[8];
    float* out = (float*)d_out;

    float *normx, *uvqk, *attn, *proj, *w1, *w2;
    cudaGetSymbolAddress((void**)&normx, g_normx);
    cudaGetSymbolAddress((void**)&uvqk,  g_uvqk);
    cudaGetSymbolAddress((void**)&attn,  g_attn);
    cudaGetSymbolAddress((void**)&proj,  g_proj);
    cudaGetSymbolAddress((void**)&w1,    g_w1);
    cudaGetSymbolAddress((void**)&w2,    g_w2);

    // idempotent, capture-safe; no static state
    cudaFuncSetAttribute(attn_tc_kernel,
                         cudaFuncAttributeMaxDynamicSharedMemorySize,
                         ATTN_SMEM_BYTES);
    cudaFuncSetAttribute(gemm_tf32_kernel,
                         cudaFuncAttributeMaxDynamicSharedMemorySize,
                         GEMM_SMEM_BYTES);

    // 0) pre-round weights to tf32 values
    round_w_kernel<<<(Esz * N_UVQK / 4 + 255) / 256, 256>>>(uvqk_w, w1, Esz * N_UVQK / 4);
    round_w_kernel<<<(N_PROJ * Esz / 4 + 255) / 256, 256>>>(out_w, w2, N_PROJ * Esz / 4);

    // 1) LayerNorm input (tf32-rounded output)
    ln_in_kernel<<<Mrows, 256>>>(x, in_scale, in_bias, normx);

    // 2) UVQK GEMM: + beta, silu(u) tap, C stored tf32-rounded for attention
    gemm_tf32_kernel<<<dim3(N_UVQK / 128, Mrows / 128), 256, GEMM_SMEM_BYTES>>>(
        normx, w1, uvqk, Mrows, N_UVQK, Esz, uvqk_beta, nullptr, proj, 1);

    // 3) cp.async attention, 128-row q tiles (causal-skip) -> attn
    attn_tc_kernel<<<dim3(Ssz / 128, Hsz, Bsz), 256, ATTN_SMEM_BYTES>>>(
        uvqk, num_targets, attn);

    // 4) LN(attn) + gate (tf32-rounded proj entries)
    postattn_kernel<<<Mrows, 256>>>(attn, out_scale, out_bias, proj);

    // 5) output GEMM with fused residual (exact fp32 output)
    gemm_tf32_kernel<<<dim3(Esz / 128, Mrows / 128), 256, GEMM_SMEM_BYTES>>>(
        proj, w2, out, Mrows, Esz, N_PROJ, nullptr, x, nullptr, 0);
}

// round 15
// speedup vs baseline: 1.2399x; 1.0608x over previous
#include <cuda_runtime.h>
#include <math.h>
#include <stdint.h>

// ---------------- problem constants ----------------
#define Bsz   4
#define Ssz   2048
#define Esz   1024
#define Hsz   8
#define Mrows (Bsz * Ssz)          // 8192
#define N_UVQK 4096
#define N_PROJ 3072
#define ALPHA_SC 0.08838834764831845f   // 1/sqrt(128)
#define INV_S    (1.0f / 2048.0f)
#define LN_EPS   1e-6f

// ---------------- scratch (device globals; no allocation allowed) -----------
__device__ float g_normx[(size_t)Mrows * Esz];    // 32 MB (tf32-rounded)
__device__ float g_uvqk [(size_t)Mrows * N_UVQK]; // 128 MB (tf32-rounded)
__device__ float g_attn [(size_t)Mrows * Esz];    // 32 MB (full fp32)
__device__ float g_proj [(size_t)Mrows * N_PROJ]; // 96 MB (tf32-rounded)
__device__ float g_w1   [(size_t)Esz * N_UVQK];   // 16 MB rounded uvqk_w
__device__ float g_w2   [(size_t)N_PROJ * Esz];   // 12 MB rounded out_w

// ---------------- helpers ----------------
__device__ __forceinline__ uint32_t f2tf32(float x) {
    uint32_t r;
    asm("cvt.rna.tf32.f32 %0, %1;" : "=r"(r) : "f"(x));
    return r;
}
__device__ __forceinline__ float rnd32(float x) {
    return __uint_as_float(f2tf32(x));
}

__device__ __forceinline__ void mma_tf32(float* d,
    uint32_t a0, uint32_t a1, uint32_t a2, uint32_t a3,
    uint32_t b0, uint32_t b1)
{
    asm volatile(
        "mma.sync.aligned.m16n8k8.row.col.f32.tf32.tf32.f32 "
        "{%0,%1,%2,%3}, {%4,%5,%6,%7}, {%8,%9}, {%0,%1,%2,%3};\n"
        : "+f"(d[0]), "+f"(d[1]), "+f"(d[2]), "+f"(d[3])
        : "r"(a0), "r"(a1), "r"(a2), "r"(a3), "r"(b0), "r"(b1));
}

__device__ __forceinline__ float silu_f(float x) {       // exact-ish (LN paths)
    return x / (1.0f + expf(-x));
}
__device__ __forceinline__ float silu_fast(float x) {    // MUFU path (hot loops)
    return __fdividef(x, 1.0f + __expf(-x));
}

__device__ __forceinline__ uint32_t smem_u32(const void* p) {
    uint32_t a;
    asm("{ .reg .u64 t; cvta.to.shared.u64 t, %1; cvt.u32.u64 %0, t; }"
        : "=r"(a) : "l"(p));
    return a;
}

__device__ __forceinline__ void cp_async16(uint32_t dst, const void* src) {
    asm volatile("cp.async.cg.shared.global [%0], [%1], 16;\n"
                 :: "r"(dst), "l"(src));
}
#define CP_COMMIT()  asm volatile("cp.async.commit_group;\n" ::: "memory")
#define CP_WAIT1()   asm volatile("cp.async.wait_group 1;\n" ::: "memory")
#define CP_WAIT2()   asm volatile("cp.async.wait_group 2;\n" ::: "memory")

__device__ __forceinline__ void blockReduce2(float& a, float& b) {
    #pragma unroll
    for (int off = 16; off > 0; off >>= 1) {
        a += __shfl_down_sync(0xffffffffu, a, off);
        b += __shfl_down_sync(0xffffffffu, b, off);
    }
    __shared__ float sa[8], sb[8];
    __shared__ float ra, rb;
    int w = threadIdx.x >> 5, l = threadIdx.x & 31;
    if (l == 0) { sa[w] = a; sb[w] = b; }
    __syncthreads();
    if (threadIdx.x == 0) {
        float ta = 0.f, tb = 0.f;
        #pragma unroll
        for (int i = 0; i < 8; i++) { ta += sa[i]; tb += sb[i]; }
        ra = ta; rb = tb;
    }
    __syncthreads();
    a = ra; b = rb;
}

// ---------------- tf32 pre-round of weights ----------------
__global__ __launch_bounds__(256) void round_w_kernel(
    const float* __restrict__ src, float* __restrict__ dst, int n4)
{
    int i = (blockIdx.x * 256 + threadIdx.x);
    if (i < n4) {
        float4 v = *(const float4*)(src + (size_t)i * 4);
        v.x = rnd32(v.x); v.y = rnd32(v.y); v.z = rnd32(v.z); v.w = rnd32(v.w);
        *(float4*)(dst + (size_t)i * 4) = v;
    }
}

// ---------------- LayerNorm on input x -> g_normx (tf32-rounded) -----------
__global__ __launch_bounds__(256) void ln_in_kernel(
    const float* __restrict__ x, const float* __restrict__ sc,
    const float* __restrict__ bi, float* __restrict__ out)
{
    int row = blockIdx.x;
    int c = threadIdx.x * 4;
    const float* xr = x + (size_t)row * Esz;
    float4 v = *(const float4*)&xr[c];
    float s  = v.x + v.y + v.z + v.w;
    float ss = v.x*v.x + v.y*v.y + v.z*v.z + v.w*v.w;
    blockReduce2(s, ss);
    float mu = s * (1.0f / Esz);
    float rs = rsqrtf(ss * (1.0f / Esz) - mu * mu + LN_EPS);
    float4 s4 = *(const float4*)&sc[c];
    float4 b4 = *(const float4*)&bi[c];
    float4 o;
    o.x = rnd32((v.x - mu) * rs * s4.x + b4.x);
    o.y = rnd32((v.y - mu) * rs * s4.y + b4.y);
    o.z = rnd32((v.z - mu) * rs * s4.z + b4.z);
    o.w = rnd32((v.w - mu) * rs * s4.w + b4.w);
    *(float4*)&out[(size_t)row * Esz + c] = o;
}

// ---------------- tf32 mma.sync GEMM, cp.async 3-stage (R12 config) ---------
#define GSTG_WORDS 4672
#define GEMM_SMEM_BYTES (3 * GSTG_WORDS * 4)   // 56064 B

__global__ __launch_bounds__(256, 2) void gemm_tf32_kernel(
    const float* __restrict__ A, const float* __restrict__ Bm,
    float* __restrict__ C, int M, int N, int K,
    const float* __restrict__ bias, const float* __restrict__ resid,
    float* __restrict__ silu_dst, int round_c)
{
    extern __shared__ __align__(16) uint32_t gsm[];
    uint32_t sbase = smem_u32(gsm);

    int tid = threadIdx.x;
    int wid = tid >> 5, lane = tid & 31;
    int gID = lane >> 2, tig = lane & 3;
    int warpM = wid & 1, warpN = wid >> 1;
    int bx = blockIdx.x, by = blockIdx.y;

    int arow = tid >> 1, acol = (tid & 1) * 8;
    int brow = tid >> 4, bcol = (tid & 15) * 8;
    const float* Abase = A + (size_t)(by * 128 + arow) * K + acol;
    const float* Bbase = Bm + (size_t)brow * N + bx * 128 + bcol;

    int nIter = K >> 4;

    auto issue_stage = [&](int c) {
        int s = c - (c / 3) * 3;
        uint32_t ab = sbase + (uint32_t)(s * GSTG_WORDS) * 4;
        uint32_t bb = ab + 2560 * 4;
        const float* ag = Abase + c * 16;
        cp_async16(ab + (uint32_t)(arow * 20 + acol) * 4, ag);
        cp_async16(ab + (uint32_t)(arow * 20 + acol + 4) * 4, ag + 4);
        const float* bg = Bbase + (size_t)(c * 16) * N;
        cp_async16(bb + (uint32_t)(brow * 132 + bcol) * 4, bg);
        cp_async16(bb + (uint32_t)(brow * 132 + bcol + 4) * 4, bg + 4);
    };

    float acc[4][4][4];
    #pragma unroll
    for (int i = 0; i < 4; i++)
        #pragma unroll
        for (int j = 0; j < 4; j++)
            #pragma unroll
            for (int q = 0; q < 4; q++) acc[i][j][q] = 0.f;

    issue_stage(0); CP_COMMIT();
    issue_stage(1); CP_COMMIT();

    for (int c = 0; c < nIter; c++) {
        CP_WAIT1();
        __syncthreads();
        if (c + 2 < nIter) issue_stage(c + 2);
        CP_COMMIT();

        int s = c - (c / 3) * 3;
        const uint32_t* As = gsm + s * GSTG_WORDS;
        const uint32_t* Bs = As + 2560;
        #pragma unroll
        for (int ks = 0; ks < 2; ks++) {
            int kb = ks * 8;
            uint32_t af[4][4], bf[4][2];
            #pragma unroll
            for (int i = 0; i < 4; i++) {
                int m = warpM * 64 + i * 16 + gID;
                af[i][0] = As[m * 20 + kb + tig];
                af[i][1] = As[(m + 8) * 20 + kb + tig];
                af[i][2] = As[m * 20 + kb + tig + 4];
                af[i][3] = As[(m + 8) * 20 + kb + tig + 4];
            }
            #pragma unroll
            for (int j = 0; j < 4; j++) {
                int n = warpN * 32 + j * 8 + gID;
                bf[j][0] = Bs[(kb + tig) * 132 + n];
                bf[j][1] = Bs[(kb + tig + 4) * 132 + n];
            }
            #pragma unroll
            for (int i = 0; i < 4; i++)
                #pragma unroll
                for (int j = 0; j < 4; j++)
                    mma_tf32(acc[i][j], af[i][0], af[i][1], af[i][2], af[i][3],
                             bf[j][0], bf[j][1]);
        }
    }

    // epilogue
    bool siluTile = (silu_dst != nullptr) && (bx * 128 < 1024);
    #pragma unroll
    for (int i = 0; i < 4; i++) {
        int r0 = by * 128 + warpM * 64 + i * 16 + gID;
        #pragma unroll
        for (int j = 0; j < 4; j++) {
            int cg = bx * 128 + warpN * 32 + j * 8 + tig * 2;
            float v0 = acc[i][j][0], v1 = acc[i][j][1];
            float v2 = acc[i][j][2], v3 = acc[i][j][3];
            if (bias) {
                float b0 = bias[cg], b1 = bias[cg + 1];
                v0 += b0; v1 += b1; v2 += b0; v3 += b1;
            }
            size_t o0 = (size_t)r0 * N + cg;
            size_t o1 = (size_t)(r0 + 8) * N + cg;
            if (resid) {
                v0 += resid[o0]; v1 += resid[o0 + 1];
                v2 += resid[o1]; v3 += resid[o1 + 1];
            }
            if (round_c) {
                *(float2*)&C[o0] = make_float2(rnd32(v0), rnd32(v1));
                *(float2*)&C[o1] = make_float2(rnd32(v2), rnd32(v3));
            } else {
                *(float2*)&C[o0] = make_float2(v0, v1);
                *(float2*)&C[o1] = make_float2(v2, v3);
            }
            if (siluTile) {
                size_t p0 = (size_t)r0 * N_PROJ + cg;
                size_t p1 = (size_t)(r0 + 8) * N_PROJ + cg;
                *(float2*)&silu_dst[p0] =
                    make_float2(rnd32(silu_fast(v0)), rnd32(silu_fast(v1)));
                *(float2*)&silu_dst[p1] =
                    make_float2(rnd32(silu_fast(v2)), rnd32(silu_fast(v3)));
            }
        }
    }
}

// ---------------- cp.async-pipelined attention, 128-row Q tiles -------------
// block = (b, h, 128 q rows). 256 threads / 8 warps: 4(M) x 2(N).
// Score warp tile 32x32; W@V warp tile 32x64. K double-buffered w/ lookahead;
// V single-buffered (latency hidden under score phase).
#define AQ(r,c)    sm[(r) * 132 + (c)]
#define AK(s,r,c)  sm[16896 + (s) * 8448 + (r) * 132 + (c)]
#define AV(r,c)    sm[33792 + (r) * 132 + (c)]
#define AW(r,c)    sm[42240 + (r) * 68 + (c)]
#define ATTN_SMEM_BYTES (50944 * 4)

__global__ __launch_bounds__(256) void attn_tc_kernel(
    const float* __restrict__ uvqk, const int* __restrict__ num_targets,
    float* __restrict__ attn_out)
{
    extern __shared__ uint32_t sm[];
    uint32_t sbase = smem_u32(sm);
    int tid = threadIdx.x;
    int wid = tid >> 5, lane = tid & 31;
    int gID = lane >> 2, tig = lane & 3;
    int b = blockIdx.z, h = blockIdx.y;
    int qt = (int)gridDim.x - 1 - (int)blockIdx.x;   // heavy blocks first
    int q0 = qt * 128;
    int maxid = Ssz - num_targets[b];

    const size_t rstride = N_UVQK;
    const float* qbase = uvqk + (size_t)(b * Ssz) * rstride + 2048 + h * 128;
    const float* kbase = uvqk + (size_t)(b * Ssz) * rstride + 3072 + h * 128;
    const float* vbase = uvqk + (size_t)(b * Ssz) * rstride + 1024 + h * 128;

    int ldr = tid >> 2, ldc = (tid & 3) * 32;   // 64-row tile loader
    int qr = tid >> 1, qc = (tid & 1) * 64;     // 128-row Q loader

    // Q tile 128x128 via cp.async (group 0)
    {
        const float* qsrc = qbase + (size_t)(q0 + qr) * rstride + qc;
        #pragma unroll
        for (int x = 0; x < 16; x++)
            cp_async16(sbase + (uint32_t)(qr * 132 + qc + x * 4) * 4,
                       qsrc + x * 4);
    }
    CP_COMMIT();

    auto issue_k = [&](int t) {
        int s = t & 1;
        const float* ksrc = kbase + (size_t)(t * 64 + ldr) * rstride + ldc;
        uint32_t kdst = sbase + (uint32_t)(16896 + s * 8448 + ldr * 132 + ldc) * 4;
        #pragma unroll
        for (int x = 0; x < 8; x++)
            cp_async16(kdst + x * 16, ksrc + x * 4);
    };
    auto issue_v = [&](int t) {
        const float* vsrc = vbase + (size_t)(t * 64 + ldr) * rstride + ldc;
        uint32_t vdst = sbase + (uint32_t)(33792 + ldr * 132 + ldc) * 4;
        #pragma unroll
        for (int x = 0; x < 8; x++)
            cp_async16(vdst + x * 16, vsrc + x * 4);
    };

    issue_k(0); CP_COMMIT();       // group 1

    int wM = wid & 3, wN = wid >> 2;

    float acc_o[2][8][4];
    #pragma unroll
    for (int i = 0; i < 2; i++)
        #pragma unroll
        for (int j = 0; j < 8; j++)
            #pragma unroll
            for (int q = 0; q < 4; q++) acc_o[i][j][q] = 0.f;

    int ntiles = q0 / 64 + 2;       // k tiles: k0 <= q0 + 64

    for (int t = 0; t < ntiles; t++) {
        int s = t & 1;
        __syncthreads();    // V buffer + Ws free; K stage s free
        issue_v(t); CP_COMMIT();
        if (t + 1 < ntiles) issue_k(t + 1);
        CP_COMMIT();        // always commit (empty tail keeps group count)
        CP_WAIT2();         // K(t) + Q resident; V(t), K(t+1) may be in flight
        __syncthreads();    // visibility of K(t)

        // scores: S(128x64) = Q(128x128) @ K^T; warp tile 32x32
        float acc_s[2][4][4];
        #pragma unroll
        for (int i = 0; i < 2; i++)
            #pragma unroll
            for (int j = 0; j < 4; j++)
                #pragma unroll
                for (int q = 0; q < 4; q++) acc_s[i][j][q] = 0.f;

        #pragma unroll
        for (int ks = 0; ks < 16; ks++) {
            int kb = ks * 8;
            uint32_t af[2][4];
            #pragma unroll
            for (int i = 0; i < 2; i++) {
                int m = wM * 32 + i * 16 + gID;
                af[i][0] = AQ(m, kb + tig);
                af[i][1] = AQ(m + 8, kb + tig);
                af[i][2] = AQ(m, kb + tig + 4);
                af[i][3] = AQ(m + 8, kb + tig + 4);
            }
            #pragma unroll
            for (int j = 0; j < 4; j++) {
                int n = wN * 32 + j * 8 + gID;
                uint32_t b0 = AK(s, n, kb + tig);
                uint32_t b1 = AK(s, n, kb + tig + 4);
                #pragma unroll
                for (int i = 0; i < 2; i++)
                    mma_tf32(acc_s[i][j], af[i][0], af[i][1], af[i][2], af[i][3],
                             b0, b1);
            }
        }

        // mask + silu -> Ws
        {
            int k0 = t * 64;
            bool interior = (k0 + 64 <= q0);   // all kg < qg in this tile
            if (interior) {
                // valid <=> kg < maxid  (proof: kg<qg => min(qg,m)>min(kg,m) <=> kg<m)
                #pragma unroll
                for (int i = 0; i < 2; i++) {
                    int rowL = wM * 32 + i * 16 + gID;
                    #pragma unroll
                    for (int j = 0; j < 4; j++) {
                        int colL = wN * 32 + j * 8 + tig * 2;
                        #pragma unroll
                        for (int cc = 0; cc < 2; cc++) {
                            int kg = k0 + colL + cc;
                            bool vld = (kg < maxid);
                            float s0 = acc_s[i][j][cc] * ALPHA_SC;
                            float s1 = acc_s[i][j][cc + 2] * ALPHA_SC;
                            float w0 = vld ? silu_fast(s0) * INV_S : 0.f;
                            float w1 = vld ? silu_fast(s1) * INV_S : 0.f;
                            AW(rowL, colL + cc)     = f2tf32(w0);
                            AW(rowL + 8, colL + cc) = f2tf32(w1);
                        }
                    }
                }
            } else {
                #pragma unroll
                for (int i = 0; i < 2; i++) {
                    int rowL = wM * 32 + i * 16 + gID;
                    int qg0 = q0 + rowL;
                    int qg1 = qg0 + 8;
                    int idq0 = min(qg0, maxid);
                    int idq1 = min(qg1, maxid);
                    #pragma unroll
                    for (int j = 0; j < 4; j++) {
                        int colL = wN * 32 + j * 8 + tig * 2;
                        #pragma unroll
                        for (int cc = 0; cc < 2; cc++) {
                            int kg = k0 + colL + cc;
                            int idk = min(kg, maxid);
                            float s0 = acc_s[i][j][cc] * ALPHA_SC;
                            float s1 = acc_s[i][j][cc + 2] * ALPHA_SC;
                            bool v0 = (qg0 == kg) || (idq0 > idk);
                            bool v1 = (qg1 == kg) || (idq1 > idk);
                            float w0 = v0 ? silu_fast(s0) * INV_S : 0.f;
                            float w1 = v1 ? silu_fast(s1) * INV_S : 0.f;
                            AW(rowL, colL + cc)     = f2tf32(w0);
                            AW(rowL + 8, colL + cc) = f2tf32(w1);
                        }
                    }
                }
            }
        }
        CP_WAIT1();         // V(t) resident; only K(t+1) may remain in flight
        __syncthreads();    // Ws + V visible to all warps

        // O += Ws(128x64) @ V(64x128); warp tile 32x64
        #pragma unroll
        for (int ks = 0; ks < 8; ks++) {
            int kb = ks * 8;
            uint32_t af[2][4];
            #pragma unroll
            for (int i = 0; i < 2; i++) {
                int m = wM * 32 + i * 16 + gID;
                af[i][0] = AW(m, kb + tig);
                af[i][1] = AW(m + 8, kb + tig);
                af[i][2] = AW(m, kb + tig + 4);
                af[i][3] = AW(m + 8, kb + tig + 4);
            }
            #pragma unroll
            for (int j = 0; j < 8; j++) {
                int n = wN * 64 + j * 8 + gID;
                uint32_t b0 = AV(kb + tig, n);
                uint32_t b1 = AV(kb + tig + 4, n);
                #pragma unroll
                for (int i = 0; i < 2; i++)
                    mma_tf32(acc_o[i][j], af[i][0], af[i][1], af[i][2], af[i][3],
                             b0, b1);
            }
        }
    }

    // epilogue
    #pragma unroll
    for (int i = 0; i < 2; i++) {
        int rowL = wM * 32 + i * 16 + gID;
        size_t grow0 = (size_t)(b * Ssz + q0 + rowL) * Esz;
        size_t grow1 = (size_t)(b * Ssz + q0 + rowL + 8) * Esz;
        #pragma unroll
        for (int j = 0; j < 8; j++) {
            int col = h * 128 + wN * 64 + j * 8 + tig * 2;
            *(float2*)&attn_out[grow0 + col] = make_float2(acc_o[i][j][0], acc_o[i][j][1]);
            *(float2*)&attn_out[grow1 + col] = make_float2(acc_o[i][j][2], acc_o[i][j][3]);
        }
    }
}

// ---------------- post-attention: LN(attn), gate, fill proj (tf32-rounded) --
__global__ __launch_bounds__(256) void postattn_kernel(
    const float* __restrict__ attn, const float* __restrict__ sc,
    const float* __restrict__ bi, float* __restrict__ proj)
{
    int row = blockIdx.x;
    int c = threadIdx.x * 4;
    const float* ar = attn + (size_t)row * Esz;
    float4 a = *(const float4*)&ar[c];
    float s  = a.x + a.y + a.z + a.w;
    float ss = a.x*a.x + a.y*a.y + a.z*a.z + a.w*a.w;
    blockReduce2(s, ss);
    float mu = s * (1.0f / Esz);
    float rs = rsqrtf(ss * (1.0f / Esz) - mu * mu + LN_EPS);
    float4 s4 = *(const float4*)&sc[c];
    float4 b4 = *(const float4*)&bi[c];
    float4 n;
    n.x = (a.x - mu) * rs * s4.x + b4.x;
    n.y = (a.y - mu) * rs * s4.y + b4.y;
    n.z = (a.z - mu) * rs * s4.z + b4.z;
    n.w = (a.w - mu) * rs * s4.w + b4.w;
    float* pr = proj + (size_t)row * N_PROJ;
    float4 u = *(const float4*)&pr[c];         // silu(u), already tf32-rounded
    float4 ar4;
    ar4.x = rnd32(a.x); ar4.y = rnd32(a.y); ar4.z = rnd32(a.z); ar4.w = rnd32(a.w);
    *(float4*)&pr[1024 + c] = ar4;
    float4 g;
    g.x = rnd32(u.x * n.x); g.y = rnd32(u.y * n.y);
    g.z = rnd32(u.z * n.z); g.w = rnd32(u.w * n.w);
    *(float4*)&pr[2048 + c] = g;
}

// ---------------- launch ----------------
extern "C" void kernel_launch(void* const* d_in, const int* in_sizes, int n_in,
                              void* d_out, int out_size)
{
    const float* x           = (const float*)d_in[0];
    const int*   num_targets = (const int*)  d_in[1];
    const float* uvqk_w      = (const float*)d_in[2];
    const float* uvqk_beta   = (const float*)d_in[3];
    const float* out_w       = (const float*)d_in[4];
    const float* in_scale    = (const float*)d_in[5];
    const float* in_bias     = (const float*)d_in[6];
    const float* out_scale   = (const float*)d_in[7];
    const float* out_bias    = (const float*)d_in[8];
    float* out = (float*)d_out;

    float *normx, *uvqk, *attn, *proj, *w1, *w2;
    cudaGetSymbolAddress((void**)&normx, g_normx);
    cudaGetSymbolAddress((void**)&uvqk,  g_uvqk);
    cudaGetSymbolAddress((void**)&attn,  g_attn);
    cudaGetSymbolAddress((void**)&proj,  g_proj);
    cudaGetSymbolAddress((void**)&w1,    g_w1);
    cudaGetSymbolAddress((void**)&w2,    g_w2);

    // idempotent, capture-safe; no static state
    cudaFuncSetAttribute(attn_tc_kernel,
                         cudaFuncAttributeMaxDynamicSharedMemorySize,
                         ATTN_SMEM_BYTES);
    cudaFuncSetAttribute(gemm_tf32_kernel,
                         cudaFuncAttributeMaxDynamicSharedMemorySize,
                         GEMM_SMEM_BYTES);

    // 0) pre-round weights to tf32 values
    round_w_kernel<<<(Esz * N_UVQK / 4 + 255) / 256, 256>>>(uvqk_w, w1, Esz * N_UVQK / 4);
    round_w_kernel<<<(N_PROJ * Esz / 4 + 255) / 256, 256>>>(out_w, w2, N_PROJ * Esz / 4);

    // 1) LayerNorm input (tf32-rounded output)
    ln_in_kernel<<<Mrows, 256>>>(x, in_scale, in_bias, normx);

    // 2) UVQK GEMM: + beta, silu(u) tap, C stored tf32-rounded for attention
    gemm_tf32_kernel<<<dim3(N_UVQK / 128, Mrows / 128), 256, GEMM_SMEM_BYTES>>>(
        normx, w1, uvqk, Mrows, N_UVQK, Esz, uvqk_beta, nullptr, proj, 1);

    // 3) cp.async attention, 128-row q tiles (causal-skip) -> attn
    attn_tc_kernel<<<dim3(Ssz / 128, Hsz, Bsz), 256, ATTN_SMEM_BYTES>>>(
        uvqk, num_targets, attn);

    // 4) LN(attn) + gate (tf32-rounded proj entries)
    postattn_kernel<<<Mrows, 256>>>(attn, out_scale, out_bias, proj);

    // 5) output GEMM with fused residual (exact fp32 output)
    gemm_tf32_kernel<<<dim3(Esz / 128, Mrows / 128), 256, GEMM_SMEM_BYTES>>>(
        proj, w2, out, Mrows, Esz, N_PROJ, nullptr, x, nullptr, 0);
}

// round 17
// speedup vs baseline: 1.2856x; 1.0368x over previous
#include <cuda_runtime.h>
#include <math.h>
#include <stdint.h>

// ---------------- problem constants ----------------
#define Bsz   4
#define Ssz   2048
#define Esz   1024
#define Hsz   8
#define Mrows (Bsz * Ssz)          // 8192
#define N_UVQK 4096
#define N_PROJ 3072
#define ALPHA_SC 0.08838834764831845f   // 1/sqrt(128)
#define INV_S    (1.0f / 2048.0f)
#define LN_EPS   1e-6f

// ---------------- scratch (device globals; no allocation allowed) -----------
__device__ float g_normx[(size_t)Mrows * Esz];    // 32 MB (tf32-rounded)
__device__ float g_uvqk [(size_t)Mrows * N_UVQK]; // 128 MB (tf32-rounded)
__device__ float g_attn [(size_t)Mrows * Esz];    // 32 MB (full fp32)
__device__ float g_proj [(size_t)Mrows * N_PROJ]; // 96 MB (tf32-rounded)
__device__ float g_w1   [(size_t)Esz * N_UVQK];   // 16 MB rounded uvqk_w
__device__ float g_w2   [(size_t)N_PROJ * Esz];   // 12 MB rounded out_w

// ---------------- helpers ----------------
__device__ __forceinline__ uint32_t f2tf32(float x) {
    uint32_t r;
    asm("cvt.rna.tf32.f32 %0, %1;" : "=r"(r) : "f"(x));
    return r;
}
__device__ __forceinline__ float rnd32(float x) {
    return __uint_as_float(f2tf32(x));
}

__device__ __forceinline__ void mma_tf32(float* d,
    uint32_t a0, uint32_t a1, uint32_t a2, uint32_t a3,
    uint32_t b0, uint32_t b1)
{
    asm volatile(
        "mma.sync.aligned.m16n8k8.row.col.f32.tf32.tf32.f32 "
        "{%0,%1,%2,%3}, {%4,%5,%6,%7}, {%8,%9}, {%0,%1,%2,%3};\n"
        : "+f"(d[0]), "+f"(d[1]), "+f"(d[2]), "+f"(d[3])
        : "r"(a0), "r"(a1), "r"(a2), "r"(a3), "r"(b0), "r"(b1));
}

// ldmatrix x4: each "m8n8 b16 matrix" row = 16 B = 4 tf32 words.
// Thread t receives word t%4 of row t/4 of its matrix.
__device__ __forceinline__ void ldsm_x4(uint32_t* r, uint32_t addr) {
    asm volatile(
        "ldmatrix.sync.aligned.m8n8.x4.shared.b16 {%0,%1,%2,%3}, [%4];"
        : "=r"(r[0]), "=r"(r[1]), "=r"(r[2]), "=r"(r[3]) : "r"(addr));
}

__device__ __forceinline__ float silu_f(float x) {       // exact-ish (LN paths)
    return x / (1.0f + expf(-x));
}
__device__ __forceinline__ float silu_fast(float x) {    // MUFU path (hot loops)
    return __fdividef(x, 1.0f + __expf(-x));
}

__device__ __forceinline__ uint32_t smem_u32(const void* p) {
    uint32_t a;
    asm("{ .reg .u64 t; cvta.to.shared.u64 t, %1; cvt.u32.u64 %0, t; }"
        : "=r"(a) : "l"(p));
    return a;
}

__device__ __forceinline__ void cp_async16(uint32_t dst, const void* src) {
    asm volatile("cp.async.cg.shared.global [%0], [%1], 16;\n"
                 :: "r"(dst), "l"(src));
}
#define CP_COMMIT()  asm volatile("cp.async.commit_group;\n" ::: "memory")
#define CP_WAIT1()   asm volatile("cp.async.wait_group 1;\n" ::: "memory")
#define CP_WAIT2()   asm volatile("cp.async.wait_group 2;\n" ::: "memory")

__device__ __forceinline__ void blockReduce2(float& a, float& b) {
    #pragma unroll
    for (int off = 16; off > 0; off >>= 1) {
        a += __shfl_down_sync(0xffffffffu, a, off);
        b += __shfl_down_sync(0xffffffffu, b, off);
    }
    __shared__ float sa[8], sb[8];
    __shared__ float ra, rb;
    int w = threadIdx.x >> 5, l = threadIdx.x & 31;
    if (l == 0) { sa[w] = a; sb[w] = b; }
    __syncthreads();
    if (threadIdx.x == 0) {
        float ta = 0.f, tb = 0.f;
        #pragma unroll
        for (int i = 0; i < 8; i++) { ta += sa[i]; tb += sb[i]; }
        ra = ta; rb = tb;
    }
    __syncthreads();
    a = ra; b = rb;
}

// ---------------- tf32 pre-round of weights ----------------
__global__ __launch_bounds__(256) void round_w_kernel(
    const float* __restrict__ src, float* __restrict__ dst, int n4)
{
    int i = (blockIdx.x * 256 + threadIdx.x);
    if (i < n4) {
        float4 v = *(const float4*)(src + (size_t)i * 4);
        v.x = rnd32(v.x); v.y = rnd32(v.y); v.z = rnd32(v.z); v.w = rnd32(v.w);
        *(float4*)(dst + (size_t)i * 4) = v;
    }
}

// ---------------- LayerNorm on input x -> g_normx (tf32-rounded) -----------
__global__ __launch_bounds__(256) void ln_in_kernel(
    const float* __restrict__ x, const float* __restrict__ sc,
    const float* __restrict__ bi, float* __restrict__ out)
{
    int row = blockIdx.x;
    int c = threadIdx.x * 4;
    const float* xr = x + (size_t)row * Esz;
    float4 v = *(const float4*)&xr[c];
    float s  = v.x + v.y + v.z + v.w;
    float ss = v.x*v.x + v.y*v.y + v.z*v.z + v.w*v.w;
    blockReduce2(s, ss);
    float mu = s * (1.0f / Esz);
    float rs = rsqrtf(ss * (1.0f / Esz) - mu * mu + LN_EPS);
    float4 s4 = *(const float4*)&sc[c];
    float4 b4 = *(const float4*)&bi[c];
    float4 o;
    o.x = rnd32((v.x - mu) * rs * s4.x + b4.x);
    o.y = rnd32((v.y - mu) * rs * s4.y + b4.y);
    o.z = rnd32((v.z - mu) * rs * s4.z + b4.z);
    o.w = rnd32((v.w - mu) * rs * s4.w + b4.w);
    *(float4*)&out[(size_t)row * Esz + c] = o;
}

// ---------------- tf32 mma.sync GEMM, cp.async 3-stage + ldmatrix A ---------
#define GSTG_WORDS 4672
#define GEMM_SMEM_BYTES (3 * GSTG_WORDS * 4)   // 56064 B

__global__ __launch_bounds__(256, 2) void gemm_tf32_kernel(
    const float* __restrict__ A, const float* __restrict__ Bm,
    float* __restrict__ C, int M, int N, int K,
    const float* __restrict__ bias, const float* __restrict__ resid,
    float* __restrict__ silu_dst, int round_c)
{
    extern __shared__ __align__(16) uint32_t gsm[];
    uint32_t sbase = smem_u32(gsm);

    int tid = threadIdx.x;
    int wid = tid >> 5, lane = tid & 31;
    int gID = lane >> 2, tig = lane & 3;
    int warpM = wid & 1, warpN = wid >> 1;
    int bx = blockIdx.x, by = blockIdx.y;

    // ldmatrix lane mapping for A-type fragments (row-major, k contiguous)
    int lrow = lane & 15;
    int lcol = (lane >> 4) << 2;

    int arow = tid >> 1, acol = (tid & 1) * 8;
    int brow = tid >> 4, bcol = (tid & 15) * 8;
    const float* Abase = A + (size_t)(by * 128 + arow) * K + acol;
    const float* Bbase = Bm + (size_t)brow * N + bx * 128 + bcol;

    int nIter = K >> 4;

    auto issue_stage = [&](int c) {
        int s = c - (c / 3) * 3;
        uint32_t ab = sbase + (uint32_t)(s * GSTG_WORDS) * 4;
        uint32_t bb = ab + 2560 * 4;
        const float* ag = Abase + c * 16;
        cp_async16(ab + (uint32_t)(arow * 20 + acol) * 4, ag);
        cp_async16(ab + (uint32_t)(arow * 20 + acol + 4) * 4, ag + 4);
        const float* bg = Bbase + (size_t)(c * 16) * N;
        cp_async16(bb + (uint32_t)(brow * 132 + bcol) * 4, bg);
        cp_async16(bb + (uint32_t)(brow * 132 + bcol + 4) * 4, bg + 4);
    };

    float acc[4][4][4];
    #pragma unroll
    for (int i = 0; i < 4; i++)
        #pragma unroll
        for (int j = 0; j < 4; j++)
            #pragma unroll
            for (int q = 0; q < 4; q++) acc[i][j][q] = 0.f;

    issue_stage(0); CP_COMMIT();
    issue_stage(1); CP_COMMIT();

    for (int c = 0; c < nIter; c++) {
        CP_WAIT1();
        __syncthreads();
        if (c + 2 < nIter) issue_stage(c + 2);
        CP_COMMIT();

        int s = c - (c / 3) * 3;
        const uint32_t* Bs = gsm + s * GSTG_WORDS + 2560;
        uint32_t aFragBase = sbase
            + (uint32_t)((s * GSTG_WORDS + (warpM * 64 + lrow) * 20 + lcol) << 2);
        #pragma unroll
        for (int ks = 0; ks < 2; ks++) {
            int kb = ks * 8;
            uint32_t af[4][4], bf[4][2];
            #pragma unroll
            for (int i = 0; i < 4; i++)
                ldsm_x4(af[i], aFragBase + (uint32_t)((i * 16 * 20 + kb) << 2));
            #pragma unroll
            for (int j = 0; j < 4; j++) {
                int n = warpN * 32 + j * 8 + gID;
                bf[j][0] = Bs[(kb + tig) * 132 + n];
                bf[j][1] = Bs[(kb + tig + 4) * 132 + n];
            }
            #pragma unroll
            for (int i = 0; i < 4; i++)
                #pragma unroll
                for (int j = 0; j < 4; j++)
                    mma_tf32(acc[i][j], af[i][0], af[i][1], af[i][2], af[i][3],
                             bf[j][0], bf[j][1]);
        }
    }

    // epilogue
    bool siluTile = (silu_dst != nullptr) && (bx * 128 < 1024);
    #pragma unroll
    for (int i = 0; i < 4; i++) {
        int r0 = by * 128 + warpM * 64 + i * 16 + gID;
        #pragma unroll
        for (int j = 0; j < 4; j++) {
            int cg = bx * 128 + warpN * 32 + j * 8 + tig * 2;
            float v0 = acc[i][j][0], v1 = acc[i][j][1];
            float v2 = acc[i][j][2], v3 = acc[i][j][3];
            if (bias) {
                float b0 = bias[cg], b1 = bias[cg + 1];
                v0 += b0; v1 += b1; v2 += b0; v3 += b1;
            }
            size_t o0 = (size_t)r0 * N + cg;
            size_t o1 = (size_t)(r0 + 8) * N + cg;
            if (resid) {
                v0 += resid[o0]; v1 += resid[o0 + 1];
                v2 += resid[o1]; v3 += resid[o1 + 1];
            }
            if (round_c) {
                *(float2*)&C[o0] = make_float2(rnd32(v0), rnd32(v1));
                *(float2*)&C[o1] = make_float2(rnd32(v2), rnd32(v3));
            } else {
                *(float2*)&C[o0] = make_float2(v0, v1);
                *(float2*)&C[o1] = make_float2(v2, v3);
            }
            if (siluTile) {
                size_t p0 = (size_t)r0 * N_PROJ + cg;
                size_t p1 = (size_t)(r0 + 8) * N_PROJ + cg;
                *(float2*)&silu_dst[p0] =
                    make_float2(rnd32(silu_fast(v0)), rnd32(silu_fast(v1)));
                *(float2*)&silu_dst[p1] =
                    make_float2(rnd32(silu_fast(v2)), rnd32(silu_fast(v3)));
            }
        }
    }
}

// ---------------- cp.async-pipelined attention, 128-row Q tiles + ldmatrix --
#define AQ(r,c)    sm[(r) * 132 + (c)]
#define AK(s,r,c)  sm[16896 + (s) * 8448 + (r) * 132 + (c)]
#define AV(r,c)    sm[33792 + (r) * 132 + (c)]
#define AW(r,c)    sm[42240 + (r) * 68 + (c)]
#define ATTN_SMEM_BYTES (50944 * 4)

__global__ __launch_bounds__(256) void attn_tc_kernel(
    const float* __restrict__ uvqk, const int* __restrict__ num_targets,
    float* __restrict__ attn_out)
{
    extern __shared__ uint32_t sm[];
    uint32_t sbase = smem_u32(sm);
    int tid = threadIdx.x;
    int wid = tid >> 5, lane = tid & 31;
    int gID = lane >> 2, tig = lane & 3;
    int b = blockIdx.z, h = blockIdx.y;
    int qt = (int)gridDim.x - 1 - (int)blockIdx.x;   // heavy blocks first
    int q0 = qt * 128;
    int maxid = Ssz - num_targets[b];

    // ldmatrix lane mappings
    int lrow = lane & 15;                    // A-type frags (Q, Ws)
    int lcol = (lane >> 4) << 2;
    int krow = (lane & 7) + ((lane >> 4) & 1) * 8;   // K x4 (j-pair pack)
    int kcol = ((lane >> 3) & 1) * 4;

    const size_t rstride = N_UVQK;
    const float* qbase = uvqk + (size_t)(b * Ssz) * rstride + 2048 + h * 128;
    const float* kbase = uvqk + (size_t)(b * Ssz) * rstride + 3072 + h * 128;
    const float* vbase = uvqk + (size_t)(b * Ssz) * rstride + 1024 + h * 128;

    int ldr = tid >> 2, ldc = (tid & 3) * 32;   // 64-row tile loader
    int qr = tid >> 1, qc = (tid & 1) * 64;     // 128-row Q loader

    // Q tile 128x128 via cp.async (group 0)
    {
        const float* qsrc = qbase + (size_t)(q0 + qr) * rstride + qc;
        #pragma unroll
        for (int x = 0; x < 16; x++)
            cp_async16(sbase + (uint32_t)(qr * 132 + qc + x * 4) * 4,
                       qsrc + x * 4);
    }
    CP_COMMIT();

    auto issue_k = [&](int t) {
        int s = t & 1;
        const float* ksrc = kbase + (size_t)(t * 64 + ldr) * rstride + ldc;
        uint32_t kdst = sbase + (uint32_t)(16896 + s * 8448 + ldr * 132 + ldc) * 4;
        #pragma unroll
        for (int x = 0; x < 8; x++)
            cp_async16(kdst + x * 16, ksrc + x * 4);
    };
    auto issue_v = [&](int t) {
        const float* vsrc = vbase + (size_t)(t * 64 + ldr) * rstride + ldc;
        uint32_t vdst = sbase + (uint32_t)(33792 + ldr * 132 + ldc) * 4;
        #pragma unroll
        for (int x = 0; x < 8; x++)
            cp_async16(vdst + x * 16, vsrc + x * 4);
    };

    issue_k(0); CP_COMMIT();       // group 1

    int wM = wid & 3, wN = wid >> 2;

    float acc_o[2][8][4];
    #pragma unroll
    for (int i = 0; i < 2; i++)
        #pragma unroll
        for (int j = 0; j < 8; j++)
            #pragma unroll
            for (int q = 0; q < 4; q++) acc_o[i][j][q] = 0.f;

    int ntiles = q0 / 64 + 2;       // k tiles: k0 <= q0 + 64

    uint32_t qFragBase = sbase + (uint32_t)(((wM * 32 + lrow) * 132 + lcol) << 2);
    uint32_t wFragBase = sbase + (uint32_t)((42240 + (wM * 32 + lrow) * 68 + lcol) << 2);

    for (int t = 0; t < ntiles; t++) {
        int s = t & 1;
        __syncthreads();    // V buffer + Ws free; K stage s free
        issue_v(t); CP_COMMIT();
        if (t + 1 < ntiles) issue_k(t + 1);
        CP_COMMIT();        // always commit (empty tail keeps group count)
        CP_WAIT2();         // K(t) + Q resident; V(t), K(t+1) may be in flight
        __syncthreads();    // visibility of K(t)

        uint32_t kFragBase = sbase
            + (uint32_t)((16896 + s * 8448 + (wN * 32 + krow) * 132 + kcol) << 2);

        // scores: S(128x64) = Q(128x128) @ K^T; warp tile 32x32
        float acc_s[2][4][4];
        #pragma unroll
        for (int i = 0; i < 2; i++)
            #pragma unroll
            for (int j = 0; j < 4; j++)
                #pragma unroll
                for (int q = 0; q < 4; q++) acc_s[i][j][q] = 0.f;

        #pragma unroll
        for (int ks = 0; ks < 16; ks++) {
            int kb = ks * 8;
            uint32_t af[2][4], bf[4][2];
            #pragma unroll
            for (int i = 0; i < 2; i++)
                ldsm_x4(af[i], qFragBase + (uint32_t)((i * 16 * 132 + kb) << 2));
            #pragma unroll
            for (int p = 0; p < 2; p++) {
                uint32_t tmp[4];
                ldsm_x4(tmp, kFragBase + (uint32_t)((p * 16 * 132 + kb) << 2));
                bf[2 * p][0] = tmp[0]; bf[2 * p][1] = tmp[1];
                bf[2 * p + 1][0] = tmp[2]; bf[2 * p + 1][1] = tmp[3];
            }
            #pragma unroll
            for (int j = 0; j < 4; j++)
                #pragma unroll
                for (int i = 0; i < 2; i++)
                    mma_tf32(acc_s[i][j], af[i][0], af[i][1], af[i][2], af[i][3],
                             bf[j][0], bf[j][1]);
        }

        // mask + silu -> Ws
        {
            int k0 = t * 64;
            bool interior = (k0 + 64 <= q0);   // all kg < qg in this tile
            if (interior) {
                // valid <=> kg < maxid
                #pragma unroll
                for (int i = 0; i < 2; i++) {
                    int rowL = wM * 32 + i * 16 + gID;
                    #pragma unroll
                    for (int j = 0; j < 4; j++) {
                        int colL = wN * 32 + j * 8 + tig * 2;
                        #pragma unroll
                        for (int cc = 0; cc < 2; cc++) {
                            int kg = k0 + colL + cc;
                            bool vld = (kg < maxid);
                            float s0 = acc_s[i][j][cc] * ALPHA_SC;
                            float s1 = acc_s[i][j][cc + 2] * ALPHA_SC;
                            float w0 = vld ? silu_fast(s0) * INV_S : 0.f;
                            float w1 = vld ? silu_fast(s1) * INV_S : 0.f;
                            AW(rowL, colL + cc)     = f2tf32(w0);
                            AW(rowL + 8, colL + cc) = f2tf32(w1);
                        }
                    }
                }
            } else {
                #pragma unroll
                for (int i = 0; i < 2; i++) {
                    int rowL = wM * 32 + i * 16 + gID;
                    int qg0 = q0 + rowL;
                    int qg1 = qg0 + 8;
                    int idq0 = min(qg0, maxid);
                    int idq1 = min(qg1, maxid);
                    #pragma unroll
                    for (int j = 0; j < 4; j++) {
                        int colL = wN * 32 + j * 8 + tig * 2;
                        #pragma unroll
                        for (int cc = 0; cc < 2; cc++) {
                            int kg = k0 + colL + cc;
                            int idk = min(kg, maxid);
                            float s0 = acc_s[i][j][cc] * ALPHA_SC;
                            float s1 = acc_s[i][j][cc + 2] * ALPHA_SC;
                            bool v0 = (qg0 == kg) || (idq0 > idk);
                            bool v1 = (qg1 == kg) || (idq1 > idk);
                            float w0 = v0 ? silu_fast(s0) * INV_S : 0.f;
                            float w1 = v1 ? silu_fast(s1) * INV_S : 0.f;
                            AW(rowL, colL + cc)     = f2tf32(w0);
                            AW(rowL + 8, colL + cc) = f2tf32(w1);
                        }
                    }
                }
            }
        }
        CP_WAIT1();         // V(t) resident; only K(t+1) may remain in flight
        __syncthreads();    // Ws + V visible to all warps

        // O += Ws(128x64) @ V(64x128); warp tile 32x64
        #pragma unroll
        for (int ks = 0; ks < 8; ks++) {
            int kb = ks * 8;
            uint32_t af[2][4];
            #pragma unroll
            for (int i = 0; i < 2; i++)
                ldsm_x4(af[i], wFragBase + (uint32_t)((i * 16 * 68 + kb) << 2));
            #pragma unroll
            for (int j = 0; j < 8; j++) {
                int n = wN * 64 + j * 8 + gID;
                uint32_t b0 = AV(kb + tig, n);
                uint32_t b1 = AV(kb + tig + 4, n);
                #pragma unroll
                for (int i = 0; i < 2; i++)
                    mma_tf32(acc_o[i][j], af[i][0], af[i][1], af[i][2], af[i][3],
                             b0, b1);
            }
        }
    }

    // epilogue
    #pragma unroll
    for (int i = 0; i < 2; i++) {
        int rowL = wM * 32 + i * 16 + gID;
        size_t grow0 = (size_t)(b * Ssz + q0 + rowL) * Esz;
        size_t grow1 = (size_t)(b * Ssz + q0 + rowL + 8) * Esz;
        #pragma unroll
        for (int j = 0; j < 8; j++) {
            int col = h * 128 + wN * 64 + j * 8 + tig * 2;
            *(float2*)&attn_out[grow0 + col] = make_float2(acc_o[i][j][0], acc_o[i][j][1]);
            *(float2*)&attn_out[grow1 + col] = make_float2(acc_o[i][j][2], acc_o[i][j][3]);
        }
    }
}

// ---------------- post-attention: LN(attn), gate, fill proj (tf32-rounded) --
__global__ __launch_bounds__(256) void postattn_kernel(
    const float* __restrict__ attn, const float* __restrict__ sc,
    const float* __restrict__ bi, float* __restrict__ proj)
{
    int row = blockIdx.x;
    int c = threadIdx.x * 4;
    const float* ar = attn + (size_t)row * Esz;
    float4 a = *(const float4*)&ar[c];
    float s  = a.x + a.y + a.z + a.w;
    float ss = a.x*a.x + a.y*a.y + a.z*a.z + a.w*a.w;
    blockReduce2(s, ss);
    float mu = s * (1.0f / Esz);
    float rs = rsqrtf(ss * (1.0f / Esz) - mu * mu + LN_EPS);
    float4 s4 = *(const float4*)&sc[c];
    float4 b4 = *(const float4*)&bi[c];
    float4 n;
    n.x = (a.x - mu) * rs * s4.x + b4.x;
    n.y = (a.y - mu) * rs * s4.y + b4.y;
    n.z = (a.z - mu) * rs * s4.z + b4.z;
    n.w = (a.w - mu) * rs * s4.w + b4.w;
    float* pr = proj + (size_t)row * N_PROJ;
    float4 u = *(const float4*)&pr[c];         // silu(u), already tf32-rounded
    float4 ar4;
    ar4.x = rnd32(a.x); ar4.y = rnd32(a.y); ar4.z = rnd32(a.z); ar4.w = rnd32(a.w);
    *(float4*)&pr[1024 + c] = ar4;
    float4 g;
    g.x = rnd32(u.x * n.x); g.y = rnd32(u.y * n.y);
    g.z = rnd32(u.z * n.z); g.w = rnd32(u.w * n.w);
    *(float4*)&pr[2048 + c] = g;
}

// ---------------- launch ----------------
extern "C" void kernel_launch(void* const* d_in, const int* in_sizes, int n_in,
                              void* d_out, int out_size)
{
    const float* x           = (const float*)d_in[0];
    const int*   num_targets = (const int*)  d_in[1];
    const float* uvqk_w      = (const float*)d_in[2];
    const float* uvqk_beta   = (const float*)d_in[3];
    const float* out_w       = (const float*)d_in[4];
    const float* in_scale    = (const float*)d_in[5];
    const float* in_bias     = (const float*)d_in[6];
    const float* out_scale   = (const float*)d_in[7];
    const float* out_bias    = (const float*)d_in[8];
    float* out = (float*)d_out;

    float *normx, *uvqk, *attn, *proj, *w1, *w2;
    cudaGetSymbolAddress((void**)&normx, g_normx);
    cudaGetSymbolAddress((void**)&uvqk,  g_uvqk);
    cudaGetSymbolAddress((void**)&attn,  g_attn);
    cudaGetSymbolAddress((void**)&proj,  g_proj);
    cudaGetSymbolAddress((void**)&w1,    g_w1);
    cudaGetSymbolAddress((void**)&w2,    g_w2);

    // idempotent, capture-safe; no static state
    cudaFuncSetAttribute(attn_tc_kernel,
                         cudaFuncAttributeMaxDynamicSharedMemorySize,
                         ATTN_SMEM_BYTES);
    cudaFuncSetAttribute(gemm_tf32_kernel,
                         cudaFuncAttributeMaxDynamicSharedMemorySize,
                         GEMM_SMEM_BYTES);

    // 0) pre-round weights to tf32 values
    round_w_kernel<<<(Esz * N_UVQK / 4 + 255) / 256, 256>>>(uvqk_w, w1, Esz * N_UVQK / 4);
    round_w_kernel<<<(N_PROJ * Esz / 4 + 255) / 256, 256>>>(out_w, w2, N_PROJ * Esz / 4);

    // 1) LayerNorm input (tf32-rounded output)
    ln_in_kernel<<<Mrows, 256>>>(x, in_scale, in_bias, normx);

    // 2) UVQK GEMM: + beta, silu(u) tap, C stored tf32-rounded for attention
    gemm_tf32_kernel<<<dim3(N_UVQK / 128, Mrows / 128), 256, GEMM_SMEM_BYTES>>>(
        normx, w1, uvqk, Mrows, N_UVQK, Esz, uvqk_beta, nullptr, proj, 1);

    // 3) cp.async attention, 128-row q tiles (causal-skip) -> attn
    attn_tc_kernel<<<dim3(Ssz / 128, Hsz, Bsz), 256, ATTN_SMEM_BYTES>>>(
        uvqk, num_targets, attn);

    // 4) LN(attn) + gate (tf32-rounded proj entries)
    postattn_kernel<<<Mrows, 256>>>(attn, out_scale, out_bias, proj);

    // 5) output GEMM with fused residual (exact fp32 output)
    gemm_tf32_kernel<<<dim3(Esz / 128, Mrows / 128), 256, GEMM_SMEM_BYTES>>>(
        proj, w2, out, Mrows, Esz, N_PROJ, nullptr, x, nullptr, 0);
}